// round 2
// baseline (speedup 1.0000x reference)
#include <cuda_runtime.h>

#define Nn 80
#define Fh 64
#define Hh 256
#define Zz 128
#define OFFS 3160
#define Eg 800
#define ITERS 50
#define NB 16
#define AB 5     // Nn / NB columns of 'a' per CTA
#define NT 512

// ---------------- device scratch (static, allocation-free) ----------------
__device__ float g_Ag[Nn*Nn];     // normalized adjacency (GCN propagation)
__device__ float g_T[Nn*Hh];
__device__ float g_U[Nn*Hh];
__device__ float g_H[Nn*Hh];
__device__ float g_he[Hh];
__device__ float g_B[Nn*Nn];      // B' : sigmoid logits off-diag, 0 diag
__device__ float g_A[Nn*Nn];      // A' : 0/1 off-diag, 0 diag
__device__ float g_ns[Nn*Nn];     // node_sim[i][a]
__device__ float g_X0[Nn*Nn];
__device__ float g_X1[Nn*Nn];
__device__ unsigned g_bar;
__device__ unsigned g_maxbits[ITERS+1];

// ---------------- setup: degrees, normalized adjacency, A' ----------------
__global__ void k_setup(const int* __restrict__ ei, const int* __restrict__ adj) {
    __shared__ int se[2*Eg];
    __shared__ int cnt[Nn];
    __shared__ float dinv[Nn];
    int t = threadIdx.x;
    for (int idx = t; idx < 2*Eg; idx += 256) se[idx] = ei[idx];
    if (t < Nn) cnt[t] = 1;               // self loop
    __syncthreads();
    for (int e = t; e < Eg; e += 256) atomicAdd(&cnt[se[Eg+e]], 1);
    __syncthreads();
    if (t < Nn) dinv[t] = rsqrtf((float)cnt[t]);
    // zero B' and build A'
    for (int idx = t; idx < Nn*Nn; idx += 256) {
        g_B[idx] = 0.f;
        int i = idx / Nn, j = idx % Nn;
        g_A[idx] = (i != j && ((adj[i*Nn+j] | adj[j*Nn+i]) != 0)) ? 1.f : 0.f;
    }
    __syncthreads();
    if (t < Nn) {
        float di = dinv[t];
        float* Agr = &g_Ag[t*Nn];
        for (int j = 0; j < Nn; ++j) Agr[j] = 0.f;
        for (int e = 0; e < Eg; ++e) {
            if (se[Eg+e] == t) {
                int s = se[e];
                Agr[s] += dinv[s] * di;
            }
        }
        Agr[t] += di * di;                // self loop
    }
}

// ---------------- T = src @ W  (src row-major [Nn,K], W [K,Hh]) -----------
__global__ void k_xw(const float* __restrict__ xin, const float* __restrict__ W,
                     int K, int useH) {
    __shared__ float xr[Hh];
    int row = blockIdx.x, f = threadIdx.x;
    const float* src = useH ? g_H : xin;
    for (int k = f; k < K; k += 256) xr[k] = src[row*K + k];
    __syncthreads();
    float acc = 0.f;
    for (int k = 0; k < K; ++k) acc += xr[k] * W[k*Hh + f];
    g_T[row*Hh + f] = acc;
}

// ---------------- U = Ag @ T + bias ----------------
__global__ void k_agg(const float* __restrict__ bias) {
    __shared__ float ar[Nn];
    int row = blockIdx.x, f = threadIdx.x;
    if (f < Nn) ar[f] = g_Ag[row*Nn + f];
    __syncthreads();
    float acc = bias[f];
    for (int j = 0; j < Nn; ++j) acc += ar[j] * g_T[j*Hh + f];
    g_U[row*Hh + f] = acc;
}

// ---------------- H = relu(batchnorm(U)) ----------------
__global__ void k_bn(const float* __restrict__ gam, const float* __restrict__ bet) {
    int f = threadIdx.x;
    float s = 0.f;
    for (int i = 0; i < Nn; ++i) s += g_U[i*Hh + f];
    float m = s * (1.f / Nn);
    float v = 0.f;
    for (int i = 0; i < Nn; ++i) { float d = g_U[i*Hh + f] - m; v += d*d; }
    v *= (1.f / Nn);
    float sc = gam[f] * rsqrtf(v + 1e-5f), bo = bet[f];
    for (int i = 0; i < Nn; ++i) {
        float h = (g_U[i*Hh + f] - m) * sc + bo;
        g_H[i*Hh + f] = fmaxf(h, 0.f);
    }
}

// ---------------- pooling, reparam, decoder hidden ----------------
__global__ void k_head(const float* __restrict__ Wmu, const float* __restrict__ bmu,
                       const float* __restrict__ Wlv, const float* __restrict__ blv,
                       const float* __restrict__ eps, const float* __restrict__ We1,
                       const float* __restrict__ be1) {
    __shared__ float gv[Hh];
    __shared__ float zv[Zz];
    int t = threadIdx.x;
    float s = 0.f;
    for (int i = 0; i < Nn; ++i) s += g_H[i*Hh + t];
    gv[t] = s * (1.f / Nn);
    __syncthreads();
    if (t < Zz) {
        float mu = bmu[t], lv = blv[t];
        for (int f = 0; f < Hh; ++f) { mu += gv[f]*Wmu[f*Zz + t]; lv += gv[f]*Wlv[f*Zz + t]; }
        lv = fminf(fmaxf(lv, -4.f), 4.f);
        zv[t] = mu + eps[t] * expf(0.5f * lv);
    }
    __syncthreads();
    float h = be1[t];
    for (int z = 0; z < Zz; ++z) h += zv[z] * We1[z*Hh + t];
    g_he[t] = fmaxf(h, 0.f);
}

// ---------------- vec_logits -> sigmoid -> B' (symmetric, zero diag) ------
__global__ void k_dec(const float* __restrict__ We2, const float* __restrict__ be2) {
    __shared__ float he[Hh];
    int t = threadIdx.x;
    he[t] = g_he[t];
    __syncthreads();
    int o = blockIdx.x * 256 + t;
    if (o < OFFS) {
        float acc = be2[o];
        for (int h = 0; h < Hh; ++h) acc += he[h] * We2[h*OFFS + o];
        float sg = 1.f / (1.f + expf(-acc));
        int i = 0, rem = o;
        while (rem >= (Nn - 1) - i) { rem -= (Nn - 1) - i; ++i; }
        int j = i + 1 + rem;
        g_B[i*Nn + j] = sg;
        g_B[j*Nn + i] = sg;
    }
}

// ---------------- node_sim, X0, barrier/scale init ----------------
__global__ void k_ns() {
    __shared__ float dA[Nn], dB[Nn];
    int t = threadIdx.x;
    if (t < Nn) {
        float sa = 1.f, sb = 1.f;
        for (int j = 0; j < Nn; ++j) { sa += g_A[t*Nn + j]; sb += g_B[t*Nn + j]; }
        dA[t] = sa; dB[t] = sb;
    }
    if (t >= 1 && t <= ITERS) g_maxbits[t] = 0u;
    if (t == 0) { g_bar = 0u; g_maxbits[0] = __float_as_uint(1.f / Nn); }
    __syncthreads();
    for (int idx = t; idx < Nn*Nn; idx += 256) {
        int i = idx / Nn, a = idx % Nn;
        g_ns[idx] = 1.f / (fabsf(dA[i] - dB[a]) + 1.f);
        g_X0[idx] = 1.f / Nn;
    }
}

// ---------------- persistent MPM: 50 iterations, 1 global sync each -------
__global__ void __launch_bounds__(NT, 1) k_mpm(float* __restrict__ out) {
    extern __shared__ float sm[];
    float* Xs = sm;                   // [Nn][81]
    float* As = sm + Nn*81;           // [Nn][81]
    float* Ms = As + Nn*81;           // [AB][81]
    __shared__ float red[32];
    const int tid = threadIdx.x, cta = blockIdx.x;
    const int a0 = cta * AB;

    // static operands into SMEM / registers
    for (int idx = tid; idx < Nn*Nn; idx += NT)
        As[(idx / Nn)*81 + (idx % Nn)] = g_A[idx];
    float nsv = 0.f;
    int i2 = 0, r2 = 0, r1 = 0, j1 = 0;
    if (tid < Nn*AB) {
        i2 = tid / AB; r2 = tid - i2*AB;
        r1 = tid / Nn; j1 = tid - r1*Nn;
        nsv = g_ns[i2*Nn + a0 + r2];
    }
    __syncthreads();

    for (int it = 0; it < ITERS; ++it) {
        const float* Xin = (it & 1) ? g_X1 : g_X0;
        float* Xout      = (it & 1) ? g_X0 : g_X1;
        // exact power-of-2 rescale from previous iteration's max
        unsigned mb = *(volatile unsigned*)&g_maxbits[it];
        float scale = __uint_as_float((254u - ((mb >> 23) & 0xffu)) << 23);

        for (int idx = tid; idx < Nn*Nn; idx += NT) {
            float v = __ldcg(&Xin[idx]);
            Xs[(idx / Nn)*81 + (idx % Nn)] = v * scale;
        }
        __syncthreads();

        // step 1: M[r][j] = max_b B'[a0+r][b] * X[j][b]
        if (tid < Nn*AB) {
            const float* Brow = &g_B[(a0 + r1)*Nn];
            const float* Xrow = &Xs[j1*81];
            float m = 0.f;
            #pragma unroll 8
            for (int b = 0; b < Nn; ++b) m = fmaxf(m, Brow[b] * Xrow[b]);
            Ms[r1*81 + j1] = m;
        }
        __syncthreads();

        // step 2: Xn[i][a0+r] = X[i][a0+r]*ns + sum_j A'[i][j]*M[r][j]
        float lmax = 0.f;
        if (tid < Nn*AB) {
            const float* Arow = &As[i2*81];
            const float* Mrow = &Ms[r2*81];
            float acc = Xs[i2*81 + a0 + r2] * nsv;
            #pragma unroll 8
            for (int j = 0; j < Nn; ++j) acc += Arow[j] * Mrow[j];
            Xout[i2*Nn + a0 + r2] = acc;
            lmax = acc;
        }
        __threadfence();   // own STG of Xout ordered before barrier arrive

        // CTA max-reduce -> one atomicMax per CTA
        for (int o = 16; o; o >>= 1) lmax = fmaxf(lmax, __shfl_xor_sync(0xffffffffu, lmax, o));
        if ((tid & 31) == 0) red[tid >> 5] = lmax;
        __syncthreads();
        if (tid == 0) {
            float bm = red[0];
            for (int w = 1; w < NT/32; ++w) bm = fmaxf(bm, red[w]);
            atomicMax(&g_maxbits[it + 1], __float_as_uint(bm));
            __threadfence();
            atomicAdd(&g_bar, 1u);
            unsigned tgt = (unsigned)(NB * (it + 1));
            while (*(volatile unsigned*)&g_bar < tgt) { }
        }
        __syncthreads();
    }

    // final true L2 normalization (only CTA 0; deterministic reduction)
    if (cta == 0) {
        const float* Xf = (ITERS & 1) ? g_X1 : g_X0;
        float ss = 0.f;
        for (int idx = tid; idx < Nn*Nn; idx += NT) {
            float v = __ldcg(&Xf[idx]);
            ss += v * v;
        }
        for (int o = 16; o; o >>= 1) ss += __shfl_xor_sync(0xffffffffu, ss, o);
        if ((tid & 31) == 0) red[tid >> 5] = ss;
        __syncthreads();
        if (tid == 0) {
            float tot = 0.f;
            for (int w = 0; w < NT/32; ++w) tot += red[w];
            red[0] = 1.f / sqrtf(tot);
        }
        __syncthreads();
        float inv = red[0];
        for (int idx = tid; idx < Nn*Nn; idx += NT)
            out[idx] = __ldcg(&Xf[idx]) * inv;
    }
}

// ---------------- launch ----------------
extern "C" void kernel_launch(void* const* d_in, const int* in_sizes, int n_in,
                              void* d_out, int out_size) {
    const float* x   = (const float*)d_in[0];
    const int*   ei  = (const int*)  d_in[1];
    const int*   adj = (const int*)  d_in[2];
    const float* eps = (const float*)d_in[3];
    const float* W1  = (const float*)d_in[4];
    const float* b1  = (const float*)d_in[5];
    const float* g1  = (const float*)d_in[6];
    const float* bt1 = (const float*)d_in[7];
    const float* W2  = (const float*)d_in[8];
    const float* b2  = (const float*)d_in[9];
    const float* g2  = (const float*)d_in[10];
    const float* bt2 = (const float*)d_in[11];
    const float* Wmu = (const float*)d_in[12];
    const float* bmu = (const float*)d_in[13];
    const float* Wlv = (const float*)d_in[14];
    const float* blv = (const float*)d_in[15];
    const float* We1 = (const float*)d_in[16];
    const float* be1 = (const float*)d_in[17];
    const float* We2 = (const float*)d_in[18];
    const float* be2 = (const float*)d_in[19];
    // Wn1/bn1/Wn2/bn2 (d_in[20..23]) are dead: B's diagonal is overwritten with 1.

    k_setup<<<1, 256>>>(ei, adj);
    k_xw<<<Nn, 256>>>(x, W1, Fh, 0);
    k_agg<<<Nn, 256>>>(b1);
    k_bn<<<1, 256>>>(g1, bt1);
    k_xw<<<Nn, 256>>>(x, W2, Hh, 1);
    k_agg<<<Nn, 256>>>(b2);
    k_bn<<<1, 256>>>(g2, bt2);
    k_head<<<1, 256>>>(Wmu, bmu, Wlv, blv, eps, We1, be1);
    k_dec<<<(OFFS + 255) / 256, 256>>>(We2, be2);
    k_ns<<<1, 256>>>();

    size_t smem = (size_t)(Nn*81 + Nn*81 + AB*81) * sizeof(float);
    cudaFuncSetAttribute((const void*)k_mpm,
                         cudaFuncAttributeMaxDynamicSharedMemorySize, (int)smem);
    k_mpm<<<NB, NT, smem>>>((float*)d_out);
}